// round 11
// baseline (speedup 1.0000x reference)
#include <cuda_runtime.h>
#include <math.h>
#include <stdint.h>

// Problem constants
#define BATCH 32
#define CDIM  256
#define HW    1024            // 32*32
#define NPOS  32768           // BATCH*HW
#define KCODE 1024
#define TOTAL 8388608         // BATCH*CDIM*HW

typedef unsigned long long ull;

// Scratch (device globals; no allocation allowed)
__device__ int           g_idx[NPOS];
__device__ float         g_wsq[KCODE];
__device__ float         g_zsq[NPOS];
__device__ unsigned int  g_counts[KCODE];
__device__ float         g_partial[1024];

// Packed fp32x2 FMA (Blackwell): two independent RN FMAs per instruction.
#define FMA2(d, a, b, c) \
    asm("fma.rn.f32x2 %0, %1, %2, %3;" : "=l"(d) : "l"(a), "l"(b), "l"(c))
#define PACK_DUP(d, s) \
    asm("mov.b64 %0, {%1, %1};" : "=l"(d) : "r"(__float_as_uint(s)))
#define UNPACK2(lo, hi, s) \
    asm("mov.b64 {%0, %1}, %2;" : "=f"(lo), "=f"(hi) : "l"(s))

#define CP_ASYNC16(dst_u32, src_ptr) \
    asm volatile("cp.async.ca.shared.global [%0], [%1], 16;" :: "r"(dst_u32), "l"(src_ptr))
#define CP_COMMIT() asm volatile("cp.async.commit_group;")
#define CP_WAIT0()  asm volatile("cp.async.wait_group 0;")

// ---------------------------------------------------------------------------
// Kernel W: per-code squared norms (one warp per code) + zero counts.
// ---------------------------------------------------------------------------
__global__ __launch_bounds__(256) void k_wsq(const float* __restrict__ w) {
    if (blockIdx.x < 4) g_counts[blockIdx.x * 256 + threadIdx.x] = 0u;
    int warp = (blockIdx.x * 256 + threadIdx.x) >> 5;   // 0..1023
    int lane = threadIdx.x & 31;
    const float* row = w + (size_t)warp * CDIM;
    float s = 0.f;
    #pragma unroll
    for (int j = 0; j < CDIM / 32; ++j) {
        float v = row[lane + j * 32];
        s = fmaf(v, v, s);
    }
    #pragma unroll
    for (int off = 16; off > 0; off >>= 1)
        s += __shfl_down_sync(0xFFFFFFFFu, s, off);
    if (lane == 0) g_wsq[warp] = s;
}

// ---------------------------------------------------------------------------
__global__ __launch_bounds__(256) void k_zsq(const float* __restrict__ z) {
    __shared__ float sm[256][33];   // [channel][position], padded
    const int t   = threadIdx.x;
    const int n0  = blockIdx.x * 32;
    const int b   = n0 >> 10;
    const int hw0 = n0 & 1023;
    const float* zb = z + (size_t)b * (CDIM * HW) + hw0;

    #pragma unroll 8
    for (int it = 0; it < 32; ++it) {
        int idx = it * 256 + t;
        int c = idx >> 5, hwi = idx & 31;
        sm[c][hwi] = zb[(size_t)c * HW + hwi];
    }
    __syncthreads();

    const int wrp = t >> 5, lane = t & 31;
    for (int r = 0; r < 4; ++r) {
        const int hwi = wrp * 4 + r;
        float acc = 0.f;
        #pragma unroll
        for (int i = 0; i < 8; ++i) {
            float a = sm[32 * i + lane][hwi];
            acc = __fadd_rn(acc, __fmul_rn(a, a));
        }
        #pragma unroll
        for (int off = 16; off > 0; off >>= 1)
            acc = __fadd_rn(acc, __shfl_down_sync(0xFFFFFFFFu, acc, off));
        if (lane == 0) g_zsq[n0 + hwi] = acc;
    }
}

// ---------------------------------------------------------------------------
// Kernel A: fused fp32 GEMM + argmin, fp32x2 FMA, occupancy-3 variant.
//  - block tile 64 pos x 128 codes (grid 512); per thread 4 pos x 8 codes
//    -> 16 ull accumulators (32 regs), __launch_bounds__(256,3).
//  - hot loop per cc: 3 LDS.128 + 4 PACK + 16 FMA2.
//  - staging: cp.async z (1 x 16B/thread), LDG->STS w, 1 sync per chunk.
// acc chains are exact ascending-c scalar-RN FMA chains; dist bits match:
//   dist = RN( RN(zsq - 2*m) + wsq ), argmin ties -> lowest index.
// ---------------------------------------------------------------------------
__global__ __launch_bounds__(256, 3) void k_argmin(const float* __restrict__ z,
                                                   const float* __restrict__ w) {
    __shared__ float zs[2][16][64];
    __shared__ float ws[2][16][128];
    __shared__ ull   bests[64];

    const int t  = threadIdx.x;
    const int tx = t & 15;       // position group: 4 positions tx*4..tx*4+3
    const int ty = t >> 4;       // code group: 8 codes ty*8..ty*8+7

    const int n0  = blockIdx.x * 64;
    const int b   = n0 >> 10;
    const int hw0 = n0 & 1023;
    const float* zbase = z + (size_t)b * (CDIM * HW) + hw0;

    // staging indices
    const int zc  = t >> 4;           // 0..15 (channel within chunk)
    const int zpp = (t & 15) * 4;     // 0..60 (position quad)
    const int wk  = t >> 1;           // 0..127 (code)
    const int wq  = (t & 1) * 8;      // 0 or 8 (channel offset)

    const float* zsrc = zbase + (size_t)zc * HW + zpp;        // + c0*HW per ct
    const float* wsrc = w + (size_t)wk * CDIM + wq;           // + nk0*CDIM + nc0

    const unsigned zd[2] = {
        (unsigned)__cvta_generic_to_shared(&zs[0][zc][zpp]),
        (unsigned)__cvta_generic_to_shared(&zs[1][zc][zpp])
    };

    float zsqv[4];
    #pragma unroll
    for (int i = 0; i < 4; ++i) zsqv[i] = g_zsq[n0 + tx * 4 + i];

    float bestv[4];
    int   bestk[4];
    #pragma unroll
    for (int i = 0; i < 4; ++i) { bestv[i] = 3.4e38f; bestk[i] = 0; }

    // ---- stage chunk 0 into buffer 0 ----
    {
        CP_ASYNC16(zd[0], zsrc);
        CP_COMMIT();
        float4 wr0 = *(const float4*)wsrc;
        float4 wr1 = *(const float4*)(wsrc + 4);
        ws[0][wq + 0][wk] = wr0.x;
        ws[0][wq + 1][wk] = wr0.y;
        ws[0][wq + 2][wk] = wr0.z;
        ws[0][wq + 3][wk] = wr0.w;
        ws[0][wq + 4][wk] = wr1.x;
        ws[0][wq + 5][wk] = wr1.y;
        ws[0][wq + 6][wk] = wr1.z;
        ws[0][wq + 7][wk] = wr1.w;
        CP_WAIT0();
    }
    __syncthreads();

    int p = 0;
    for (int kt = 0; kt < KCODE / 128; ++kt) {
        const int k0 = kt * 128;
        ull acc2[4][4];   // [pos][code pair]
        #pragma unroll
        for (int i = 0; i < 4; ++i)
            #pragma unroll
            for (int j = 0; j < 4; ++j) acc2[i][j] = 0ull;

        for (int ct = 0; ct < 16; ++ct) {
            const int nxt = kt * 16 + ct + 1;
            const bool pre = (nxt < 128);
            float4 wr0, wr1;
            if (pre) {
                const int nc0 = (nxt & 15) << 4;
                const int nk0 = (nxt >> 4) << 7;
                const int np = p ^ 1;
                CP_ASYNC16(zd[np], zsrc + (size_t)nc0 * HW);
                CP_COMMIT();
                const float* wp = wsrc + (size_t)nk0 * CDIM + nc0;
                wr0 = *(const float4*)wp;
                wr1 = *(const float4*)(wp + 4);
            }

            // ---- hot loop: 3 LDS.128 + 4 PACK + 16 FMA2 per cc ----
            #pragma unroll
            for (int cc = 0; cc < 16; ++cc) {
                float4 zq = *(const float4*)&zs[p][cc][tx * 4];
                ull zda, zdb, zdc, zdd;
                PACK_DUP(zda, zq.x); PACK_DUP(zdb, zq.y);
                PACK_DUP(zdc, zq.z); PACK_DUP(zdd, zq.w);
                const ull* wrow = (const ull*)&ws[p][cc][ty * 8];
                ulonglong2 w01 = *(const ulonglong2*)(wrow + 0);
                ulonglong2 w23 = *(const ulonglong2*)(wrow + 2);
                FMA2(acc2[0][0], zda, w01.x, acc2[0][0]);
                FMA2(acc2[1][0], zdb, w01.x, acc2[1][0]);
                FMA2(acc2[2][0], zdc, w01.x, acc2[2][0]);
                FMA2(acc2[3][0], zdd, w01.x, acc2[3][0]);
                FMA2(acc2[0][1], zda, w01.y, acc2[0][1]);
                FMA2(acc2[1][1], zdb, w01.y, acc2[1][1]);
                FMA2(acc2[2][1], zdc, w01.y, acc2[2][1]);
                FMA2(acc2[3][1], zdd, w01.y, acc2[3][1]);
                FMA2(acc2[0][2], zda, w23.x, acc2[0][2]);
                FMA2(acc2[1][2], zdb, w23.x, acc2[1][2]);
                FMA2(acc2[2][2], zdc, w23.x, acc2[2][2]);
                FMA2(acc2[3][2], zdd, w23.x, acc2[3][2]);
                FMA2(acc2[0][3], zda, w23.y, acc2[0][3]);
                FMA2(acc2[1][3], zdb, w23.y, acc2[1][3]);
                FMA2(acc2[2][3], zdc, w23.y, acc2[2][3]);
                FMA2(acc2[3][3], zdd, w23.y, acc2[3][3]);
            }

            if (pre) {
                const int np = p ^ 1;
                ws[np][wq + 0][wk] = wr0.x;
                ws[np][wq + 1][wk] = wr0.y;
                ws[np][wq + 2][wk] = wr0.z;
                ws[np][wq + 3][wk] = wr0.w;
                ws[np][wq + 4][wk] = wr1.x;
                ws[np][wq + 5][wk] = wr1.y;
                ws[np][wq + 6][wk] = wr1.z;
                ws[np][wq + 7][wk] = wr1.w;
                CP_WAIT0();
                __syncthreads();
                p = np;
            }
        }

        // epilogue: codes ascend within thread (pairs 2j, 2j+1)
        #pragma unroll
        for (int j = 0; j < 4; ++j) {
            const int kk0 = k0 + ty * 8 + 2 * j;
            const float wsq0 = g_wsq[kk0];
            const float wsq1 = g_wsq[kk0 + 1];
            #pragma unroll
            for (int i = 0; i < 4; ++i) {
                float m0, m1;
                UNPACK2(m0, m1, acc2[i][j]);
                float t0 = fmaf(-2.0f, m0, zsqv[i]);
                float s0 = __fadd_rn(t0, wsq0);
                if (s0 < bestv[i]) { bestv[i] = s0; bestk[i] = kk0; }
                float t1 = fmaf(-2.0f, m1, zsqv[i]);
                float s1 = __fadd_rn(t1, wsq1);
                if (s1 < bestv[i]) { bestv[i] = s1; bestk[i] = kk0 + 1; }
            }
        }
    }

    if (t < 64) bests[t] = ~0ull;
    __syncthreads();
    #pragma unroll
    for (int i = 0; i < 4; ++i) {
        unsigned u = __float_as_uint(bestv[i]);
        u = (u & 0x80000000u) ? ~u : (u | 0x80000000u);   // order-preserving map
        ull e = ((ull)u << 32) | (unsigned)bestk[i];
        atomicMin(&bests[tx * 4 + i], e);
    }
    __syncthreads();
    if (t < 64) {
        int idx = (int)(bests[t] & 0xFFFFFFFFull);
        g_idx[n0 + t] = idx;
        atomicAdd(&g_counts[idx], 1u);
    }
}

// ---------------------------------------------------------------------------
// Kernel B: gather codebook, straight-through output, squared-diff partials.
// Fixed 8 fully-unrolled grid-stride iterations -> 8x gather MLP.
// Iteration order identical to the rolled loop -> partial sums bit-identical.
// ---------------------------------------------------------------------------
__global__ __launch_bounds__(256) void k_quant(const float* __restrict__ z,
                                               const float* __restrict__ w,
                                               float* __restrict__ out) {
    __shared__ float sm[256];
    float local = 0.f;
    const int base = blockIdx.x * 256 + threadIdx.x;
    #pragma unroll
    for (int it = 0; it < 8; ++it) {
        const int i4 = base + it * (1024 * 256);
        const int i  = i4 * 4;
        const int hw = i & 1023;
        const int c  = (i >> 10) & 255;
        const int b  = i >> 18;
        const int* ib = &g_idx[b * HW + hw];
        float4 zz = *(const float4*)(z + i);
        float q0 = w[(size_t)ib[0] * CDIM + c];
        float q1 = w[(size_t)ib[1] * CDIM + c];
        float q2 = w[(size_t)ib[2] * CDIM + c];
        float q3 = w[(size_t)ib[3] * CDIM + c];
        float4 o;
        float d;
        d = __fadd_rn(q0, -zz.x); o.x = __fadd_rn(zz.x, d); local = fmaf(d, d, local);
        d = __fadd_rn(q1, -zz.y); o.y = __fadd_rn(zz.y, d); local = fmaf(d, d, local);
        d = __fadd_rn(q2, -zz.z); o.z = __fadd_rn(zz.z, d); local = fmaf(d, d, local);
        d = __fadd_rn(q3, -zz.w); o.w = __fadd_rn(zz.w, d); local = fmaf(d, d, local);
        *(float4*)(out + i) = o;
    }
    sm[threadIdx.x] = local;
    __syncthreads();
    for (int s = 128; s > 0; s >>= 1) {
        if (threadIdx.x < s) sm[threadIdx.x] += sm[threadIdx.x + s];
        __syncthreads();
    }
    if (threadIdx.x == 0) g_partial[blockIdx.x] = sm[0];
}

// ---------------------------------------------------------------------------
__global__ __launch_bounds__(1024) void k_final(float* __restrict__ out) {
    __shared__ float sm[1024];
    const int t = threadIdx.x;

    sm[t] = g_partial[t];
    __syncthreads();
    for (int s = 512; s > 0; s >>= 1) {
        if (t < s) sm[t] += sm[t + s];
        __syncthreads();
    }
    if (t == 0) {
        float m = sm[0] / (float)TOTAL;
        out[TOTAL] = m + 0.25f * m;      // q_latent + COMMITMENT_COST * e_latent
    }
    __syncthreads();

    float p = (float)g_counts[t] * (1.0f / (float)NPOS);
    sm[t] = p * logf(p + 1e-10f);
    __syncthreads();
    for (int s = 512; s > 0; s >>= 1) {
        if (t < s) sm[t] += sm[t + s];
        __syncthreads();
    }
    if (t == 0) out[TOTAL + 1] = expf(-sm[0]);
}

// ---------------------------------------------------------------------------
extern "C" void kernel_launch(void* const* d_in, const int* in_sizes, int n_in,
                              void* d_out, int out_size) {
    const float* z = (const float*)d_in[0];
    const float* w = (const float*)d_in[1];
    float* out = (float*)d_out;

    k_wsq<<<128, 256>>>(w);
    k_zsq<<<NPOS / 32, 256>>>(z);
    k_argmin<<<NPOS / 64, 256>>>(z, w);
    k_quant<<<1024, 256>>>(z, w, out);
    k_final<<<1, 1024>>>(out);
}

// round 12
// speedup vs baseline: 1.2932x; 1.2932x over previous
#include <cuda_runtime.h>
#include <math.h>
#include <stdint.h>

// Problem constants
#define BATCH 32
#define CDIM  256
#define HW    1024            // 32*32
#define NPOS  32768           // BATCH*HW
#define KCODE 1024
#define TOTAL 8388608         // BATCH*CDIM*HW

typedef unsigned long long ull;

// Scratch (device globals; no allocation allowed)
__device__ int           g_idx[NPOS];
__device__ float         g_wsq[KCODE];
__device__ float         g_zsq[NPOS];
__device__ unsigned int  g_counts[KCODE];
__device__ float         g_partial[1024];

// Packed fp32x2 FMA (Blackwell): two independent RN FMAs per instruction.
#define FMA2(d, a, b, c) \
    asm("fma.rn.f32x2 %0, %1, %2, %3;" : "=l"(d) : "l"(a), "l"(b), "l"(c))
#define PACK_DUP(d, s) \
    asm("mov.b64 %0, {%1, %1};" : "=l"(d) : "r"(__float_as_uint(s)))
#define UNPACK2(lo, hi, s) \
    asm("mov.b64 {%0, %1}, %2;" : "=f"(lo), "=f"(hi) : "l"(s))

#define CP_ASYNC16(dst_u32, src_ptr) \
    asm volatile("cp.async.ca.shared.global [%0], [%1], 16;" :: "r"(dst_u32), "l"(src_ptr))
#define CP_COMMIT() asm volatile("cp.async.commit_group;")
#define CP_WAIT0()  asm volatile("cp.async.wait_group 0;")

// ---------------------------------------------------------------------------
// Kernel W: per-code squared norms (one warp per code) + zero counts.
// ---------------------------------------------------------------------------
__global__ __launch_bounds__(256) void k_wsq(const float* __restrict__ w) {
    if (blockIdx.x < 4) g_counts[blockIdx.x * 256 + threadIdx.x] = 0u;
    int warp = (blockIdx.x * 256 + threadIdx.x) >> 5;   // 0..1023
    int lane = threadIdx.x & 31;
    const float* row = w + (size_t)warp * CDIM;
    float s = 0.f;
    #pragma unroll
    for (int j = 0; j < CDIM / 32; ++j) {
        float v = row[lane + j * 32];
        s = fmaf(v, v, s);
    }
    #pragma unroll
    for (int off = 16; off > 0; off >>= 1)
        s += __shfl_down_sync(0xFFFFFFFFu, s, off);
    if (lane == 0) g_wsq[warp] = s;
}

// ---------------------------------------------------------------------------
__global__ __launch_bounds__(256) void k_zsq(const float* __restrict__ z) {
    __shared__ float sm[256][33];   // [channel][position], padded
    const int t   = threadIdx.x;
    const int n0  = blockIdx.x * 32;
    const int b   = n0 >> 10;
    const int hw0 = n0 & 1023;
    const float* zb = z + (size_t)b * (CDIM * HW) + hw0;

    #pragma unroll 8
    for (int it = 0; it < 32; ++it) {
        int idx = it * 256 + t;
        int c = idx >> 5, hwi = idx & 31;
        sm[c][hwi] = zb[(size_t)c * HW + hwi];
    }
    __syncthreads();

    const int wrp = t >> 5, lane = t & 31;
    for (int r = 0; r < 4; ++r) {
        const int hwi = wrp * 4 + r;
        float acc = 0.f;
        #pragma unroll
        for (int i = 0; i < 8; ++i) {
            float a = sm[32 * i + lane][hwi];
            acc = __fadd_rn(acc, __fmul_rn(a, a));
        }
        #pragma unroll
        for (int off = 16; off > 0; off >>= 1)
            acc = __fadd_rn(acc, __shfl_down_sync(0xFFFFFFFFu, acc, off));
        if (lane == 0) g_zsq[n0 + hwi] = acc;
    }
}

// ---------------------------------------------------------------------------
// Kernel A: fused fp32 GEMM + argmin — R8 configuration, verbatim (locked).
// 128 pos x 128 codes per block; 8 pos x 8 codes per thread; hot loop
// 4 LDS.128 + 8 PACK + 32 FMA2; cp.async z, LDG->STS w, 1 sync/chunk.
// dist = RN( RN(zsq - 2*m) + wsq ), argmin ties -> lowest index.
// ---------------------------------------------------------------------------
__global__ __launch_bounds__(256, 2) void k_argmin(const float* __restrict__ z,
                                                   const float* __restrict__ w) {
    __shared__ float zs[2][16][128];
    __shared__ float ws[2][16][128];
    __shared__ ull   bests[128];

    const int t  = threadIdx.x;
    const int tx = t & 15;       // position group
    const int ty = t >> 4;       // code group

    const int n0  = blockIdx.x * 128;
    const int b   = n0 >> 10;
    const int hw0 = n0 & 1023;
    const float* zbase = z + (size_t)b * (CDIM * HW) + hw0;

    const int zc = t >> 5;            // 0..7 (two z rows per thread: zc, zc+8)
    const int zp = (t & 31) * 4;      // 0..124
    const int wk = t >> 1;            // 0..127 (code)
    const int wq = (t & 1) * 8;       // 0 or 8 (channel offset)

    const float* zsrcA = zbase + (size_t)zc * HW + zp;
    const float* zsrcB = zbase + (size_t)(8 + zc) * HW + zp;
    const float* wsrc  = w + (size_t)wk * CDIM + wq;

    const unsigned zd[2][2] = {
        { (unsigned)__cvta_generic_to_shared(&zs[0][zc][zp]),
          (unsigned)__cvta_generic_to_shared(&zs[0][8 + zc][zp]) },
        { (unsigned)__cvta_generic_to_shared(&zs[1][zc][zp]),
          (unsigned)__cvta_generic_to_shared(&zs[1][8 + zc][zp]) }
    };

    float zsqv[8];
    #pragma unroll
    for (int i = 0; i < 4; ++i) {
        zsqv[i]     = g_zsq[n0 + tx * 4 + i];
        zsqv[4 + i] = g_zsq[n0 + 64 + tx * 4 + i];
    }

    float bestv[8];
    int   bestk[8];
    #pragma unroll
    for (int i = 0; i < 8; ++i) { bestv[i] = 3.4e38f; bestk[i] = 0; }

    // ---- stage chunk 0 into buffer 0 ----
    {
        CP_ASYNC16(zd[0][0], zsrcA);
        CP_ASYNC16(zd[0][1], zsrcB);
        CP_COMMIT();
        float4 wr0 = *(const float4*)wsrc;
        float4 wr1 = *(const float4*)(wsrc + 4);
        ws[0][wq + 0][wk] = wr0.x;
        ws[0][wq + 1][wk] = wr0.y;
        ws[0][wq + 2][wk] = wr0.z;
        ws[0][wq + 3][wk] = wr0.w;
        ws[0][wq + 4][wk] = wr1.x;
        ws[0][wq + 5][wk] = wr1.y;
        ws[0][wq + 6][wk] = wr1.z;
        ws[0][wq + 7][wk] = wr1.w;
        CP_WAIT0();
    }
    __syncthreads();

    int p = 0;
    for (int kt = 0; kt < KCODE / 128; ++kt) {
        const int k0 = kt * 128;
        ull acc2[4][8];
        #pragma unroll
        for (int i = 0; i < 4; ++i)
            #pragma unroll
            for (int j = 0; j < 8; ++j) acc2[i][j] = 0ull;

        for (int ct = 0; ct < 16; ++ct) {
            const int nxt = kt * 16 + ct + 1;
            const bool pre = (nxt < 128);
            float4 wr0, wr1;
            if (pre) {
                const int nc0 = (nxt & 15) << 4;
                const int nk0 = (nxt >> 4) << 7;
                const int np = p ^ 1;
                CP_ASYNC16(zd[np][0], zsrcA + (size_t)nc0 * HW);
                CP_ASYNC16(zd[np][1], zsrcB + (size_t)nc0 * HW);
                CP_COMMIT();
                const float* wp = wsrc + (size_t)nk0 * CDIM + nc0;
                wr0 = *(const float4*)wp;
                wr1 = *(const float4*)(wp + 4);
            }

            // ---- R5/R8 hot loop: 4 LDS.128 + 8 PACK + 32 FMA2 ----
            #pragma unroll
            for (int cc = 0; cc < 16; ++cc) {
                ulonglong2 za  = *(const ulonglong2*)&zs[p][cc][tx * 4];
                ulonglong2 zb2 = *(const ulonglong2*)&zs[p][cc][64 + tx * 4];
                float4 wa = *(const float4*)&ws[p][cc][ty * 4];
                float4 wb = *(const float4*)&ws[p][cc][64 + ty * 4];
                ull wd[8];
                PACK_DUP(wd[0], wa.x); PACK_DUP(wd[1], wa.y);
                PACK_DUP(wd[2], wa.z); PACK_DUP(wd[3], wa.w);
                PACK_DUP(wd[4], wb.x); PACK_DUP(wd[5], wb.y);
                PACK_DUP(wd[6], wb.z); PACK_DUP(wd[7], wb.w);
                #pragma unroll
                for (int j = 0; j < 8; ++j) {
                    FMA2(acc2[0][j], za.x,  wd[j], acc2[0][j]);
                    FMA2(acc2[1][j], za.y,  wd[j], acc2[1][j]);
                    FMA2(acc2[2][j], zb2.x, wd[j], acc2[2][j]);
                    FMA2(acc2[3][j], zb2.y, wd[j], acc2[3][j]);
                }
            }

            if (pre) {
                const int np = p ^ 1;
                ws[np][wq + 0][wk] = wr0.x;
                ws[np][wq + 1][wk] = wr0.y;
                ws[np][wq + 2][wk] = wr0.z;
                ws[np][wq + 3][wk] = wr0.w;
                ws[np][wq + 4][wk] = wr1.x;
                ws[np][wq + 5][wk] = wr1.y;
                ws[np][wq + 6][wk] = wr1.z;
                ws[np][wq + 7][wk] = wr1.w;
                CP_WAIT0();
                __syncthreads();
                p = np;
            }
        }

        // epilogue: dist = RN( RN(zsq - 2*m) + wsq ), ascending k per thread
        #pragma unroll
        for (int j = 0; j < 8; ++j) {
            const int k = k0 + ((j < 4) ? (ty * 4 + j) : (64 + ty * 4 + (j - 4)));
            const float wsq = g_wsq[k];
            #pragma unroll
            for (int i2 = 0; i2 < 4; ++i2) {
                float m0, m1;
                UNPACK2(m0, m1, acc2[i2][j]);
                const int ia = i2 * 2;
                const float zsqA = (i2 < 2) ? zsqv[i2 * 2]     : zsqv[4 + (i2 - 2) * 2];
                const float zsqB = (i2 < 2) ? zsqv[i2 * 2 + 1] : zsqv[4 + (i2 - 2) * 2 + 1];
                float t1a = fmaf(-2.0f, m0, zsqA);
                float sca = __fadd_rn(t1a, wsq);
                if (sca < bestv[ia]) { bestv[ia] = sca; bestk[ia] = k; }
                float t1b = fmaf(-2.0f, m1, zsqB);
                float scb = __fadd_rn(t1b, wsq);
                if (scb < bestv[ia + 1]) { bestv[ia + 1] = scb; bestk[ia + 1] = k; }
            }
        }
    }

    if (t < 128) bests[t] = ~0ull;
    __syncthreads();
    #pragma unroll
    for (int i = 0; i < 8; ++i) {
        const int i2 = i >> 1;
        const int lp = (i2 < 2) ? (tx * 4 + i2 * 2 + (i & 1))
                                : (64 + tx * 4 + (i2 - 2) * 2 + (i & 1));
        unsigned u = __float_as_uint(bestv[i]);
        u = (u & 0x80000000u) ? ~u : (u | 0x80000000u);
        ull e = ((ull)u << 32) | (unsigned)bestk[i];
        atomicMin(&bests[lp], e);
    }
    __syncthreads();
    if (t < 128) {
        int idx = (int)(bests[t] & 0xFFFFFFFFull);
        g_idx[n0 + t] = idx;
        atomicAdd(&g_counts[idx], 1u);
    }
}

// ---------------------------------------------------------------------------
// Kernel B: gather-transpose quantize.
// Block = 32 positions (one batch). Phase 1: coalesced row-gather of the 32
// selected codebook rows into smem (float4 from each row). Phase 2:
// elementwise straight-through with float4 z/out and conflict-free smem q.
// out = RN(z + RN(q - z)) — exact reference elementwise formula.
// ---------------------------------------------------------------------------
#define QPITCH 257
__global__ __launch_bounds__(256) void k_quant(const float* __restrict__ z,
                                               const float* __restrict__ w,
                                               float* __restrict__ out) {
    __shared__ int   sidx[32];
    __shared__ float qs[32 * QPITCH];
    __shared__ float sm[256];

    const int t  = threadIdx.x;
    const int n0 = blockIdx.x * 32;
    const int b  = n0 >> 10;
    const int hw0 = n0 & 1023;

    if (t < 32) sidx[t] = g_idx[n0 + t];
    __syncthreads();

    // Phase 1: gather 32 codebook rows, coalesced float4 row reads.
    {
        const int p  = t >> 3;          // 0..31 position
        const int cq = t & 7;           // 0..7
        const float* row = w + (size_t)sidx[p] * CDIM;
        #pragma unroll
        for (int i = 0; i < 8; ++i) {
            const int c4 = (i * 8 + cq) * 4;
            float4 v = *(const float4*)(row + c4);
            float* dst = &qs[p * QPITCH + c4];
            dst[0] = v.x; dst[1] = v.y; dst[2] = v.z; dst[3] = v.w;
        }
    }
    __syncthreads();

    // Phase 2: elementwise. Thread -> 4 consecutive hw, c = it*32 + (t>>3).
    const float* zb = z + (size_t)b * (CDIM * HW) + hw0;
    float* ob = out + (size_t)b * (CDIM * HW) + hw0;
    const int hw4 = (t & 7) * 4;
    float local = 0.f;
    #pragma unroll
    for (int it = 0; it < 8; ++it) {
        const int c = it * 32 + (t >> 3);
        float4 zz = *(const float4*)(zb + (size_t)c * HW + hw4);
        float q0 = qs[(hw4 + 0) * QPITCH + c];
        float q1 = qs[(hw4 + 1) * QPITCH + c];
        float q2 = qs[(hw4 + 2) * QPITCH + c];
        float q3 = qs[(hw4 + 3) * QPITCH + c];
        float4 o;
        float d;
        d = __fadd_rn(q0, -zz.x); o.x = __fadd_rn(zz.x, d); local = fmaf(d, d, local);
        d = __fadd_rn(q1, -zz.y); o.y = __fadd_rn(zz.y, d); local = fmaf(d, d, local);
        d = __fadd_rn(q2, -zz.z); o.z = __fadd_rn(zz.z, d); local = fmaf(d, d, local);
        d = __fadd_rn(q3, -zz.w); o.w = __fadd_rn(zz.w, d); local = fmaf(d, d, local);
        *(float4*)(ob + (size_t)c * HW + hw4) = o;
    }
    sm[t] = local;
    __syncthreads();
    for (int s = 128; s > 0; s >>= 1) {
        if (t < s) sm[t] += sm[t + s];
        __syncthreads();
    }
    if (t == 0) g_partial[blockIdx.x] = sm[0];
}

// ---------------------------------------------------------------------------
__global__ __launch_bounds__(1024) void k_final(float* __restrict__ out) {
    __shared__ float sm[1024];
    const int t = threadIdx.x;

    sm[t] = g_partial[t];
    __syncthreads();
    for (int s = 512; s > 0; s >>= 1) {
        if (t < s) sm[t] += sm[t + s];
        __syncthreads();
    }
    if (t == 0) {
        float m = sm[0] / (float)TOTAL;
        out[TOTAL] = m + 0.25f * m;      // q_latent + COMMITMENT_COST * e_latent
    }
    __syncthreads();

    float p = (float)g_counts[t] * (1.0f / (float)NPOS);
    sm[t] = p * logf(p + 1e-10f);
    __syncthreads();
    for (int s = 512; s > 0; s >>= 1) {
        if (t < s) sm[t] += sm[t + s];
        __syncthreads();
    }
    if (t == 0) out[TOTAL + 1] = expf(-sm[0]);
}

// ---------------------------------------------------------------------------
extern "C" void kernel_launch(void* const* d_in, const int* in_sizes, int n_in,
                              void* d_out, int out_size) {
    const float* z = (const float*)d_in[0];
    const float* w = (const float*)d_in[1];
    float* out = (float*)d_out;

    k_wsq<<<128, 256>>>(w);
    k_zsq<<<NPOS / 32, 256>>>(z);
    k_argmin<<<NPOS / 128, 256>>>(z, w);
    k_quant<<<NPOS / 32, 256>>>(z, w, out);
    k_final<<<1, 1024>>>(out);
}